// round 1
// baseline (speedup 1.0000x reference)
#include <cuda_runtime.h>
#include <cuda_bf16.h>
#include <math.h>

// ----------------------------------------------------------------------------
// Problem constants
//   B=4, T=2048, HIDDEN=1024, HEADS=16, HEAD_DIM=64
//   rows M = B*T = 8192
//   GEMM1: [8192,1024] @ [1024,7168] -> qkvp
//   attention over (b,h) with T=2048, d=64, no mask
//   GEMM2: [8192,5120] @ [5120,1024] + bias, A = concat(o, gelu(p))
// ----------------------------------------------------------------------------

#define M_ROWS   8192
#define HID      1024
#define QKVP_W   7168
#define T_LEN    2048

// Scratch (allowed: __device__ global arrays)
__device__ __align__(16) float g_xn[M_ROWS * HID];       // 32 MB
__device__ __align__(16) float g_qkvp[M_ROWS * QKVP_W];  // 229 MB
__device__ __align__(16) float g_o[M_ROWS * HID];        // 32 MB
__device__ float g_invf[32];

// ---------------------------------------------------------------- LayerNorm
__global__ __launch_bounds__(256)
void ln_kernel(const float* __restrict__ x, const float* __restrict__ gamma,
               const float* __restrict__ beta, float* __restrict__ xn)
{
    int row = blockIdx.x;
    const float* xr = x + (size_t)row * HID;
    float* yr = xn + (size_t)row * HID;
    int t = threadIdx.x;

    float v[4];
    float s = 0.f, ss = 0.f;
#pragma unroll
    for (int i = 0; i < 4; i++) {
        v[i] = xr[t + 256 * i];
        s += v[i];
        ss += v[i] * v[i];
    }
#pragma unroll
    for (int o = 16; o > 0; o >>= 1) {
        s  += __shfl_xor_sync(0xffffffffu, s, o);
        ss += __shfl_xor_sync(0xffffffffu, ss, o);
    }
    __shared__ float rs[8], rss[8];
    if ((t & 31) == 0) { rs[t >> 5] = s; rss[t >> 5] = ss; }
    __syncthreads();
    float S = 0.f, SS = 0.f;
#pragma unroll
    for (int i = 0; i < 8; i++) { S += rs[i]; SS += rss[i]; }

    float mu  = S * (1.0f / 1024.0f);
    float var = SS * (1.0f / 1024.0f) - mu * mu;
    float inv = rsqrtf(var + 1e-5f);
#pragma unroll
    for (int i = 0; i < 4; i++) {
        int c = t + 256 * i;
        yr[c] = (v[i] - mu) * inv * gamma[c] + beta[c];
    }
}

// ---------------------------------------------------------------- GELU
__device__ __forceinline__ float gelu1(float v)
{
    return 0.5f * v * (1.0f + erff(v * 0.7071067811865475f));
}

// ---------------------------------------------------------------- SGEMM
// C[M,N] = A[M,K] @ B[K,N] (+ bias). Tiles 128x128x16, 256 threads, 8x8/thread.
// fused==1: K=5120, A cols [0,1024) read from A (g_o, lda=1024),
//           cols [1024,5120) read from A2 (g_qkvp + col+2048, lda=7168) with gelu.
__global__ __launch_bounds__(256, 2)
void sgemm_kernel(const float* __restrict__ A,
                  const float* __restrict__ A2,
                  const float* __restrict__ B,
                  float* __restrict__ C,
                  const float* __restrict__ bias,
                  int N, int K, int fused)
{
    __shared__ float As[16][132];   // As[k][m], padded stride 132 (16B-aligned rows)
    __shared__ float Bs[16][128];   // Bs[k][n]

    int tid = threadIdx.x;
    int tx = tid & 15, ty = tid >> 4;
    int n0 = blockIdx.x * 128;
    int m0 = blockIdx.y * 128;

    int am = tid >> 2;          // 0..63  (A tile row; also row+64)
    int ak = (tid & 3) * 4;     // 0,4,8,12
    int bk = tid >> 5;          // 0..7   (B tile row; also +8)
    int bn = (tid & 31) * 4;    // 0..124

    float acc[8][8];
#pragma unroll
    for (int i = 0; i < 8; i++)
#pragma unroll
        for (int j = 0; j < 8; j++) acc[i][j] = 0.f;

    for (int k0 = 0; k0 < K; k0 += 16) {
        // ---- load A tile (transposed into As) ----
#pragma unroll
        for (int rr = 0; rr < 2; rr++) {
            int m = m0 + am + rr * 64;
            int col = k0 + ak;
            float4 av;
            if (!fused || col < 1024) {
                av = *(const float4*)(A + (size_t)m * 1024 + col);
            } else {
                av = *(const float4*)(A2 + (size_t)m * 7168 + 2048 + col);
                av.x = gelu1(av.x); av.y = gelu1(av.y);
                av.z = gelu1(av.z); av.w = gelu1(av.w);
            }
            int mm = am + rr * 64;
            As[ak + 0][mm] = av.x;
            As[ak + 1][mm] = av.y;
            As[ak + 2][mm] = av.z;
            As[ak + 3][mm] = av.w;
        }
        // ---- load B tile ----
#pragma unroll
        for (int rr = 0; rr < 2; rr++) {
            int kk = k0 + bk + rr * 8;
            *(float4*)&Bs[bk + rr * 8][bn] =
                *(const float4*)(B + (size_t)kk * N + n0 + bn);
        }
        __syncthreads();

#pragma unroll
        for (int kk = 0; kk < 16; kk++) {
            float a[8], b[8];
            *(float4*)&a[0] = *(float4*)&As[kk][ty * 4];
            *(float4*)&a[4] = *(float4*)&As[kk][64 + ty * 4];
            *(float4*)&b[0] = *(float4*)&Bs[kk][tx * 4];
            *(float4*)&b[4] = *(float4*)&Bs[kk][64 + tx * 4];
#pragma unroll
            for (int i = 0; i < 8; i++)
#pragma unroll
                for (int j = 0; j < 8; j++)
                    acc[i][j] += a[i] * b[j];
        }
        __syncthreads();
    }

    // ---- write C ----
#pragma unroll
    for (int i = 0; i < 8; i++) {
        int m = m0 + ((i < 4) ? (ty * 4 + i) : (64 + ty * 4 + i - 4));
#pragma unroll
        for (int jg = 0; jg < 2; jg++) {
            int n = n0 + jg * 64 + tx * 4;
            float4 o;
            o.x = acc[i][jg * 4 + 0];
            o.y = acc[i][jg * 4 + 1];
            o.z = acc[i][jg * 4 + 2];
            o.w = acc[i][jg * 4 + 3];
            if (bias) {
                o.x += bias[n + 0]; o.y += bias[n + 1];
                o.z += bias[n + 2]; o.w += bias[n + 3];
            }
            *(float4*)(C + (size_t)m * N + n) = o;
        }
    }
}

// ---------------------------------------------------------------- rotary
__global__ void invf_init_kernel()
{
    int j = threadIdx.x;
    if (j < 32)
        g_invf[j] = (float)exp(-(double)j * (2.302585092994045684 / 8.0)); // 10000^(-j/32)
}

__global__ __launch_bounds__(256)
void rotary_kernel(float* __restrict__ qkvp)
{
    int idx = blockIdx.x * 256 + threadIdx.x;
    int j   = idx & 31;
    int h   = (idx >> 5) & 15;
    int tk  = (idx >> 9) & 1;     // 0=q, 1=k
    int row = idx >> 10;          // 0..8191
    int t   = row & 2047;

    float invf = g_invf[j];
    float ang  = (float)t * invf;
    float c = cosf(ang), sn = sinf(ang);

    float* p = qkvp + (size_t)row * QKVP_W + tk * 1024 + h * 64;
    float x1 = p[j], x2 = p[j + 32];
    p[j]      = x1 * c - x2 * sn;
    p[j + 32] = x1 * sn + x2 * c;
}

// ---------------------------------------------------------------- attention
// One block = 64 query rows of one (b,h). Online-softmax flash loop over 32
// K/V tiles of 64 rows. 256 threads; thread (ty,tx) in 16x16 grid:
//   S phase: rows i = ty*4..+3, cols j = tx*4..+3
//   O phase: rows i = ty*4..+3, dims d = tx*4..+3
#define QT_S 68          // padded stride for transposed tiles (16B-aligned rows)
#define ATT_SMEM_BYTES ((QT_S * 64 * 3 + 64 * 64) * 4)   // 68608 B

extern __shared__ float att_sm[];

__global__ __launch_bounds__(256)
void attn_kernel(const float* __restrict__ qkvp, float* __restrict__ o_out)
{
    float* Qt = att_sm;                 // [64 d][QT_S]  Qt[d][i]
    float* Kt = Qt + QT_S * 64;         // [64 d][QT_S]  Kt[d][j]
    float* Pt = Kt + QT_S * 64;         // [64 j][QT_S]  Pt[j][i]
    float* Vs = Pt + QT_S * 64;         // [64 j][64 d]

    int tid = threadIdx.x;
    int tx = tid & 15, ty = tid >> 4;
    int bh = blockIdx.y;
    int b = bh >> 4, h = bh & 15;
    int q0 = blockIdx.x * 64;

    const float* base = qkvp + (size_t)b * T_LEN * QKVP_W + (size_t)h * 64;

    // ---- load Q tile transposed: Qt[d][i] ----
    int lr = tid >> 2;           // tile row 0..63
    int lc = (tid & 3) * 16;     // col base
    {
        const float* g = base + (size_t)(q0 + lr) * QKVP_W + lc;
#pragma unroll
        for (int c4 = 0; c4 < 4; c4++) {
            float4 qv = *(const float4*)(g + c4 * 4);
            int c = lc + c4 * 4;
            Qt[(c + 0) * QT_S + lr] = qv.x;
            Qt[(c + 1) * QT_S + lr] = qv.y;
            Qt[(c + 2) * QT_S + lr] = qv.z;
            Qt[(c + 3) * QT_S + lr] = qv.w;
        }
    }

    float m_run[4], l_run[4], Oacc[4][4];
#pragma unroll
    for (int r = 0; r < 4; r++) {
        m_run[r] = -1e30f;
        l_run[r] = 0.f;
#pragma unroll
        for (int d = 0; d < 4; d++) Oacc[r][d] = 0.f;
    }

    for (int kt = 0; kt < 32; kt++) {
        __syncthreads();   // prior iter's Pt/Vs reads done (Qt ready on iter 0)

        // ---- load K (transposed) and V tiles ----
        int j0g = kt * 64;
        const float* gk = base + 1024 + (size_t)(j0g + lr) * QKVP_W + lc;
        const float* gv = base + 2048 + (size_t)(j0g + lr) * QKVP_W + lc;
#pragma unroll
        for (int c4 = 0; c4 < 4; c4++) {
            float4 kv = *(const float4*)(gk + c4 * 4);
            int c = lc + c4 * 4;
            Kt[(c + 0) * QT_S + lr] = kv.x;
            Kt[(c + 1) * QT_S + lr] = kv.y;
            Kt[(c + 2) * QT_S + lr] = kv.z;
            Kt[(c + 3) * QT_S + lr] = kv.w;
            *(float4*)&Vs[lr * 64 + c] = *(const float4*)(gv + c4 * 4);
        }
        __syncthreads();

        // ---- S = (Q K^T) / 8 ----
        float s[4][4];
#pragma unroll
        for (int r = 0; r < 4; r++)
#pragma unroll
            for (int c = 0; c < 4; c++) s[r][c] = 0.f;

        for (int d = 0; d < 64; d++) {
            float4 qv = *(float4*)&Qt[d * QT_S + ty * 4];
            float4 kv = *(float4*)&Kt[d * QT_S + tx * 4];
            float qa[4] = {qv.x, qv.y, qv.z, qv.w};
            float ka[4] = {kv.x, kv.y, kv.z, kv.w};
#pragma unroll
            for (int r = 0; r < 4; r++)
#pragma unroll
                for (int c = 0; c < 4; c++)
                    s[r][c] += qa[r] * ka[c];
        }
#pragma unroll
        for (int r = 0; r < 4; r++)
#pragma unroll
            for (int c = 0; c < 4; c++) s[r][c] *= 0.125f;

        // ---- online softmax (row reductions over the 16 tx lanes) ----
#pragma unroll
        for (int r = 0; r < 4; r++) {
            float rm = fmaxf(fmaxf(s[r][0], s[r][1]), fmaxf(s[r][2], s[r][3]));
#pragma unroll
            for (int o = 1; o < 16; o <<= 1)
                rm = fmaxf(rm, __shfl_xor_sync(0xffffffffu, rm, o));
            float mnew = fmaxf(m_run[r], rm);
            float corr = __expf(m_run[r] - mnew);
            float rsum = 0.f;
#pragma unroll
            for (int c = 0; c < 4; c++) {
                float p = __expf(s[r][c] - mnew);
                s[r][c] = p;
                rsum += p;
            }
#pragma unroll
            for (int o = 1; o < 16; o <<= 1)
                rsum += __shfl_xor_sync(0xffffffffu, rsum, o);
            l_run[r] = l_run[r] * corr + rsum;
            m_run[r] = mnew;
#pragma unroll
            for (int d = 0; d < 4; d++) Oacc[r][d] *= corr;
            // store P transposed: Pt[j][i]
#pragma unroll
            for (int c = 0; c < 4; c++)
                Pt[(tx * 4 + c) * QT_S + ty * 4 + r] = s[r][c];
        }
        __syncthreads();

        // ---- O += P @ V ----
        for (int j = 0; j < 64; j++) {
            float4 pv = *(float4*)&Pt[j * QT_S + ty * 4];
            float4 vv = *(float4*)&Vs[j * 64 + tx * 4];
            float pa[4] = {pv.x, pv.y, pv.z, pv.w};
            float va[4] = {vv.x, vv.y, vv.z, vv.w};
#pragma unroll
            for (int r = 0; r < 4; r++)
#pragma unroll
                for (int d = 0; d < 4; d++)
                    Oacc[r][d] += pa[r] * va[d];
        }
    }

    // ---- epilogue: O /= l, write [row][h*64+d] ----
#pragma unroll
    for (int r = 0; r < 4; r++) {
        float inv = 1.0f / l_run[r];
        int trow = q0 + ty * 4 + r;
        float4 o;
        o.x = Oacc[r][0] * inv;
        o.y = Oacc[r][1] * inv;
        o.z = Oacc[r][2] * inv;
        o.w = Oacc[r][3] * inv;
        *(float4*)(o_out + ((size_t)(b * T_LEN + trow)) * HID + h * 64 + tx * 4) = o;
    }
}

// ---------------------------------------------------------------- launch
extern "C" void kernel_launch(void* const* d_in, const int* in_sizes, int n_in,
                              void* d_out, int out_size)
{
    const float* x      = (const float*)d_in[0];
    const float* gamma  = (const float*)d_in[1];
    const float* beta   = (const float*)d_in[2];
    const float* w_in   = (const float*)d_in[3];
    const float* w_out  = (const float*)d_in[4];
    const float* b_out  = (const float*)d_in[5];
    float* out = (float*)d_out;

    void *p_xn, *p_qkvp, *p_o;
    cudaGetSymbolAddress(&p_xn, g_xn);
    cudaGetSymbolAddress(&p_qkvp, g_qkvp);
    cudaGetSymbolAddress(&p_o, g_o);
    float* xn   = (float*)p_xn;
    float* qkvp = (float*)p_qkvp;
    float* oatt = (float*)p_o;

    cudaFuncSetAttribute(attn_kernel,
                         cudaFuncAttributeMaxDynamicSharedMemorySize,
                         ATT_SMEM_BYTES);

    // 1. LayerNorm
    ln_kernel<<<M_ROWS, 256>>>(x, gamma, beta, xn);

    // 2. GEMM1: qkvp = xn @ w_in   [8192,1024]x[1024,7168]
    sgemm_kernel<<<dim3(QKVP_W / 128, M_ROWS / 128), 256>>>(
        xn, nullptr, w_in, qkvp, nullptr, QKVP_W, HID, 0);

    // 3. rotary on q,k (in place)
    invf_init_kernel<<<1, 32>>>();
    rotary_kernel<<<32768, 256>>>(qkvp);

    // 4. attention -> g_o
    attn_kernel<<<dim3(T_LEN / 64, 4 * 16), 256, ATT_SMEM_BYTES>>>(qkvp, oatt);

    // 5. GEMM2: out = concat(o, gelu(p)) @ w_out + b_out   [8192,5120]x[5120,1024]
    sgemm_kernel<<<dim3(HID / 128, M_ROWS / 128), 256>>>(
        oatt, qkvp, w_out, out, b_out, HID, 5 * HID, 1);
}

// round 4
// speedup vs baseline: 1.6690x; 1.6690x over previous
#include <cuda_runtime.h>
#include <cuda_bf16.h>
#include <math.h>
#include <cstdint>

// ----------------------------------------------------------------------------
// B=4, T=2048, HIDDEN=1024, HEADS=16, HEAD_DIM=64,  M = B*T = 8192
// GEMM1: [8192,1024]@[1024,7168] -> qkvp    (mma.sync bf16x3, fp32 acc)
// attention: fp32 SIMT flash
// GEMM2: [8192,5120]@[5120,1024]+bias       (mma.sync bf16x3)
// NOTE: harness compiles PTX target sm_100 (no 'a') -> tcgen05 unavailable;
//       HMMA via mma.sync is the top usable tensor path.
// ----------------------------------------------------------------------------

#define M_ROWS   8192
#define HID      1024
#define QKVP_W   7168
#define T_LEN    2048
#define K2TOT    5120

// ------------------------------- scratch (__device__ globals are allowed)
__device__ __align__(16) float g_qkvp[M_ROWS * QKVP_W];          // 229 MB
__device__ __align__(16) float g_o[M_ROWS * HID];                // 32 MB
__device__ __align__(16) __nv_bfloat16 g_xn_hi[M_ROWS * HID];
__device__ __align__(16) __nv_bfloat16 g_xn_lo[M_ROWS * HID];
__device__ __align__(16) __nv_bfloat16 g_w1t_hi[QKVP_W * HID];   // [N,K]
__device__ __align__(16) __nv_bfloat16 g_w1t_lo[QKVP_W * HID];
__device__ __align__(16) __nv_bfloat16 g_a2_hi[M_ROWS * K2TOT];  // 84 MB
__device__ __align__(16) __nv_bfloat16 g_a2_lo[M_ROWS * K2TOT];
__device__ __align__(16) __nv_bfloat16 g_w2t_hi[HID * K2TOT];    // [N,K]
__device__ __align__(16) __nv_bfloat16 g_w2t_lo[HID * K2TOT];
__device__ float g_invf[32];

// ============================================================ PTX helpers
__device__ __forceinline__ uint32_t smem_u32(const void* p) {
    uint32_t a;
    asm("{ .reg .u64 t; cvta.to.shared.u64 t, %1; cvt.u32.u64 %0, t; }"
        : "=r"(a) : "l"(p));
    return a;
}
__device__ __forceinline__ void cp_async16(uint32_t saddr, const void* gaddr) {
    asm volatile("cp.async.cg.shared.global [%0], [%1], 16;"
                 :: "r"(saddr), "l"(gaddr));
}
#define CP_COMMIT() asm volatile("cp.async.commit_group;" ::: "memory")
#define CP_WAIT1()  asm volatile("cp.async.wait_group 1;" ::: "memory")

__device__ __forceinline__ void lds_x4(uint32_t& r0, uint32_t& r1,
                                       uint32_t& r2, uint32_t& r3, uint32_t a) {
    asm volatile("ldmatrix.sync.aligned.m8n8.x4.shared.b16 {%0,%1,%2,%3}, [%4];"
                 : "=r"(r0), "=r"(r1), "=r"(r2), "=r"(r3) : "r"(a));
}
__device__ __forceinline__ void mma_bf16(float* c, const uint32_t* a,
                                         const uint32_t* b) {
    asm volatile(
        "mma.sync.aligned.m16n8k16.row.col.f32.bf16.bf16.f32 "
        "{%0,%1,%2,%3}, {%4,%5,%6,%7}, {%8,%9}, {%0,%1,%2,%3};"
        : "+f"(c[0]), "+f"(c[1]), "+f"(c[2]), "+f"(c[3])
        : "r"(a[0]), "r"(a[1]), "r"(a[2]), "r"(a[3]), "r"(b[0]), "r"(b[1]));
}

// ============================================================ LayerNorm -> split bf16
__global__ __launch_bounds__(256)
void ln_kernel(const float* __restrict__ x, const float* __restrict__ gamma,
               const float* __restrict__ beta,
               __nv_bfloat16* __restrict__ xh, __nv_bfloat16* __restrict__ xl)
{
    int row = blockIdx.x;
    const float* xr = x + (size_t)row * HID;
    int t = threadIdx.x;
    float v[4];
    float s = 0.f, ss = 0.f;
#pragma unroll
    for (int i = 0; i < 4; i++) {
        v[i] = xr[t + 256 * i];
        s += v[i]; ss += v[i] * v[i];
    }
#pragma unroll
    for (int o = 16; o > 0; o >>= 1) {
        s  += __shfl_xor_sync(0xffffffffu, s, o);
        ss += __shfl_xor_sync(0xffffffffu, ss, o);
    }
    __shared__ float rs[8], rss[8];
    if ((t & 31) == 0) { rs[t >> 5] = s; rss[t >> 5] = ss; }
    __syncthreads();
    float S = 0.f, SS = 0.f;
#pragma unroll
    for (int i = 0; i < 8; i++) { S += rs[i]; SS += rss[i]; }
    float mu  = S * (1.0f / 1024.0f);
    float var = SS * (1.0f / 1024.0f) - mu * mu;
    float inv = rsqrtf(var + 1e-5f);
#pragma unroll
    for (int i = 0; i < 4; i++) {
        int c = t + 256 * i;
        float y = (v[i] - mu) * inv * gamma[c] + beta[c];
        __nv_bfloat16 h = __float2bfloat16(y);
        __nv_bfloat16 l = __float2bfloat16(y - __bfloat162float(h));
        xh[(size_t)row * HID + c] = h;
        xl[(size_t)row * HID + c] = l;
    }
}

// ============================================================ W [K,N] -> [N,K] hi/lo
__global__ __launch_bounds__(256)
void transpose_split_kernel(const float* __restrict__ W,
                            __nv_bfloat16* __restrict__ Th,
                            __nv_bfloat16* __restrict__ Tl, int K, int N)
{
    __shared__ float t[32][33];
    int tx = threadIdx.x & 31, ty = threadIdx.x >> 5;
    int bx = blockIdx.x, by = blockIdx.y;
    int n = bx * 32 + tx;
#pragma unroll
    for (int i = 0; i < 4; i++) {
        int k = by * 32 + ty + i * 8;
        t[ty + i * 8][tx] = W[(size_t)k * N + n];
    }
    __syncthreads();
    int k2 = by * 32 + tx;
#pragma unroll
    for (int i = 0; i < 4; i++) {
        int n2 = bx * 32 + ty + i * 8;
        float v = t[tx][ty + i * 8];
        __nv_bfloat16 h = __float2bfloat16(v);
        __nv_bfloat16 l = __float2bfloat16(v - __bfloat162float(h));
        Th[(size_t)n2 * K + k2] = h;
        Tl[(size_t)n2 * K + k2] = l;
    }
}

// ============================================================ A2 = concat(o, gelu(p)) split
__device__ __forceinline__ float gelu1(float v)
{ return 0.5f * v * (1.0f + erff(v * 0.7071067811865475f)); }

__global__ __launch_bounds__(256)
void a2_build_kernel(const float* __restrict__ o, const float* __restrict__ qkvp,
                     __nv_bfloat16* __restrict__ hi, __nv_bfloat16* __restrict__ lo)
{
    int idx = blockIdx.x * 256 + threadIdx.x;       // over 8192*1280 float4 groups
    int m = idx / 1280, c4 = idx % 1280;
    float4 v;
    if (c4 < 256) {
        v = *(const float4*)(o + (size_t)m * HID + c4 * 4);
    } else {
        v = *(const float4*)(qkvp + (size_t)m * QKVP_W + 2048 + c4 * 4);
        v.x = gelu1(v.x); v.y = gelu1(v.y); v.z = gelu1(v.z); v.w = gelu1(v.w);
    }
    float a[4] = {v.x, v.y, v.z, v.w};
    union { __nv_bfloat16 b[4]; uint2 u; } ph, pl;
#pragma unroll
    for (int i = 0; i < 4; i++) {
        __nv_bfloat16 h = __float2bfloat16(a[i]);
        ph.b[i] = h;
        pl.b[i] = __float2bfloat16(a[i] - __bfloat162float(h));
    }
    *(uint2*)(hi + (size_t)m * K2TOT + c4 * 4) = ph.u;
    *(uint2*)(lo + (size_t)m * K2TOT + c4 * 4) = pl.u;
}

// ============================================================ HMMA GEMM bf16x3
// C[M,N] = A@B^T, A=[M,K] hi/lo, B=[N,K] hi/lo. Tile 128x128x32.
// 8 warps (4m x 2n), each 32x64. 3-stage cp.async pipeline.
// smem rows: 32 bf16 = 64B data, stride 80B (conflict-free ldmatrix).
#define STAGE_B  40960                      // 4 arrays * 128 rows * 80B
#define OFF_AL   10240
#define OFF_BH   20480
#define OFF_BL   30720
#define GT_SMEM  (3 * STAGE_B)              // 122880

__global__ __launch_bounds__(256, 1)
void gemm_hmma_kernel(const __nv_bfloat16* __restrict__ Ah,
                      const __nv_bfloat16* __restrict__ Al,
                      const __nv_bfloat16* __restrict__ Bh,
                      const __nv_bfloat16* __restrict__ Bl,
                      float* __restrict__ C, const float* __restrict__ bias,
                      int N, int K)
{
    extern __shared__ __align__(1024) char sm[];
    const uint32_t smb = smem_u32(sm);

    const int tid = threadIdx.x;
    const int lane = tid & 31;
    const int wid = tid >> 5;
    const int wm = wid >> 1;          // 0..3 -> 32-row slice
    const int wn = wid & 1;           // 0..1 -> 64-col slice
    const int m0 = blockIdx.y * 128;
    const int n0 = blockIdx.x * 128;

    const int NK = K >> 5;

    // per-thread load coords (2 chunks per array)
    int r0r = tid >> 2, c0 = (tid & 3);
    int r1r = r0r + 64;

    auto load_stage = [&](int kt, int stage) {
        uint32_t sb = smb + stage * STAGE_B;
        int k0 = kt * 32;
        const __nv_bfloat16* pAh0 = Ah + (size_t)(m0 + r0r) * K + k0 + c0 * 8;
        const __nv_bfloat16* pAh1 = Ah + (size_t)(m0 + r1r) * K + k0 + c0 * 8;
        const __nv_bfloat16* pAl0 = Al + (size_t)(m0 + r0r) * K + k0 + c0 * 8;
        const __nv_bfloat16* pAl1 = Al + (size_t)(m0 + r1r) * K + k0 + c0 * 8;
        const __nv_bfloat16* pBh0 = Bh + (size_t)(n0 + r0r) * K + k0 + c0 * 8;
        const __nv_bfloat16* pBh1 = Bh + (size_t)(n0 + r1r) * K + k0 + c0 * 8;
        const __nv_bfloat16* pBl0 = Bl + (size_t)(n0 + r0r) * K + k0 + c0 * 8;
        const __nv_bfloat16* pBl1 = Bl + (size_t)(n0 + r1r) * K + k0 + c0 * 8;
        uint32_t s0 = sb + r0r * 80 + c0 * 16;
        uint32_t s1 = sb + r1r * 80 + c0 * 16;
        cp_async16(s0,           pAh0);  cp_async16(s1,           pAh1);
        cp_async16(s0 + OFF_AL,  pAl0);  cp_async16(s1 + OFF_AL,  pAl1);
        cp_async16(s0 + OFF_BH,  pBh0);  cp_async16(s1 + OFF_BH,  pBh1);
        cp_async16(s0 + OFF_BL,  pBl0);  cp_async16(s1 + OFF_BL,  pBl1);
    };

    float acc[2][8][4];
#pragma unroll
    for (int i = 0; i < 2; i++)
#pragma unroll
        for (int j = 0; j < 8; j++)
#pragma unroll
            for (int k = 0; k < 4; k++) acc[i][j][k] = 0.f;

    load_stage(0, 0); CP_COMMIT();
    load_stage(1, 1); CP_COMMIT();

    // ldmatrix lane coords
    const int a_row = (lane & 15);
    const int a_ch  = (lane >> 4);            // 0/1
    const int b_row = ((lane >> 4) << 3) + (lane & 7);
    const int b_ch  = ((lane >> 3) & 1);

    for (int kt = 0; kt < NK; kt++) {
        CP_WAIT1();
        __syncthreads();
        if (kt + 2 < NK) load_stage(kt + 2, (kt + 2) % 3);
        CP_COMMIT();

        uint32_t sb = smb + (kt % 3) * STAGE_B;
#pragma unroll
        for (int s = 0; s < 2; s++) {
            uint32_t ah[2][4], al[2][4];
#pragma unroll
            for (int mi = 0; mi < 2; mi++) {
                uint32_t addr = sb + (wm * 32 + mi * 16 + a_row) * 80
                              + (s * 2 + a_ch) * 16;
                lds_x4(ah[mi][0], ah[mi][1], ah[mi][2], ah[mi][3], addr);
                lds_x4(al[mi][0], al[mi][1], al[mi][2], al[mi][3], addr + OFF_AL);
            }
            uint32_t bh[4][4], bl[4][4];
#pragma unroll
            for (int nt = 0; nt < 4; nt++) {
                uint32_t addr = sb + OFF_BH + (wn * 64 + nt * 16 + b_row) * 80
                              + (s * 2 + b_ch) * 16;
                lds_x4(bh[nt][0], bh[nt][1], bh[nt][2], bh[nt][3], addr);
                lds_x4(bl[nt][0], bl[nt][1], bl[nt][2], bl[nt][3],
                       addr + (OFF_BL - OFF_BH));
            }
#pragma unroll
            for (int mi = 0; mi < 2; mi++)
#pragma unroll
                for (int nt = 0; nt < 4; nt++)
#pragma unroll
                    for (int half = 0; half < 2; half++) {
                        int ni = nt * 2 + half;
                        mma_bf16(acc[mi][ni], ah[mi], &bh[nt][half * 2]);
                        mma_bf16(acc[mi][ni], ah[mi], &bl[nt][half * 2]);
                        mma_bf16(acc[mi][ni], al[mi], &bh[nt][half * 2]);
                    }
        }
    }

    // ---- epilogue ----
#pragma unroll
    for (int mi = 0; mi < 2; mi++) {
        int row = m0 + wm * 32 + mi * 16 + (lane >> 2);
#pragma unroll
        for (int ni = 0; ni < 8; ni++) {
            int col = n0 + wn * 64 + ni * 8 + (lane & 3) * 2;
            float bx = 0.f, by = 0.f;
            if (bias) { bx = bias[col]; by = bias[col + 1]; }
            float2 v0 = { acc[mi][ni][0] + bx, acc[mi][ni][1] + by };
            float2 v1 = { acc[mi][ni][2] + bx, acc[mi][ni][3] + by };
            *(float2*)(C + (size_t)row * N + col) = v0;
            *(float2*)(C + (size_t)(row + 8) * N + col) = v1;
        }
    }
}

// ============================================================ rotary (fp32, in place)
__global__ void invf_init_kernel()
{
    int j = threadIdx.x;
    if (j < 32)
        g_invf[j] = (float)exp(-(double)j * (2.302585092994045684 / 8.0));
}

__global__ __launch_bounds__(256)
void rotary_kernel(float* __restrict__ qkvp)
{
    int idx = blockIdx.x * 256 + threadIdx.x;
    int j   = idx & 31;
    int h   = (idx >> 5) & 15;
    int tk  = (idx >> 9) & 1;
    int row = idx >> 10;
    int t   = row & 2047;
    float ang = (float)t * g_invf[j];
    float c = cosf(ang), sn = sinf(ang);
    float* p = qkvp + (size_t)row * QKVP_W + tk * 1024 + h * 64;
    float x1 = p[j], x2 = p[j + 32];
    p[j]      = x1 * c - x2 * sn;
    p[j + 32] = x1 * sn + x2 * c;
}

// ============================================================ attention (fp32 flash)
#define QT_S 68
#define ATT_SMEM_BYTES ((QT_S * 64 * 3 + 64 * 64) * 4)

extern __shared__ float att_sm[];

__global__ __launch_bounds__(256)
void attn_kernel(const float* __restrict__ qkvp, float* __restrict__ o_out)
{
    float* Qt = att_sm;
    float* Kt = Qt + QT_S * 64;
    float* Pt = Kt + QT_S * 64;
    float* Vs = Pt + QT_S * 64;

    int tid = threadIdx.x;
    int tx = tid & 15, ty = tid >> 4;
    int bh = blockIdx.y;
    int b = bh >> 4, h = bh & 15;
    int q0 = blockIdx.x * 64;

    const float* base = qkvp + (size_t)b * T_LEN * QKVP_W + (size_t)h * 64;

    int lr = tid >> 2;
    int lc = (tid & 3) * 16;
    {
        const float* g = base + (size_t)(q0 + lr) * QKVP_W + lc;
#pragma unroll
        for (int c4 = 0; c4 < 4; c4++) {
            float4 qv = *(const float4*)(g + c4 * 4);
            int c = lc + c4 * 4;
            Qt[(c + 0) * QT_S + lr] = qv.x;
            Qt[(c + 1) * QT_S + lr] = qv.y;
            Qt[(c + 2) * QT_S + lr] = qv.z;
            Qt[(c + 3) * QT_S + lr] = qv.w;
        }
    }

    float m_run[4], l_run[4], Oacc[4][4];
#pragma unroll
    for (int r = 0; r < 4; r++) {
        m_run[r] = -1e30f; l_run[r] = 0.f;
#pragma unroll
        for (int d = 0; d < 4; d++) Oacc[r][d] = 0.f;
    }

    for (int kt = 0; kt < 32; kt++) {
        __syncthreads();
        int j0g = kt * 64;
        const float* gk = base + 1024 + (size_t)(j0g + lr) * QKVP_W + lc;
        const float* gv = base + 2048 + (size_t)(j0g + lr) * QKVP_W + lc;
#pragma unroll
        for (int c4 = 0; c4 < 4; c4++) {
            float4 kv = *(const float4*)(gk + c4 * 4);
            int c = lc + c4 * 4;
            Kt[(c + 0) * QT_S + lr] = kv.x;
            Kt[(c + 1) * QT_S + lr] = kv.y;
            Kt[(c + 2) * QT_S + lr] = kv.z;
            Kt[(c + 3) * QT_S + lr] = kv.w;
            *(float4*)&Vs[lr * 64 + c] = *(const float4*)(gv + c4 * 4);
        }
        __syncthreads();

        float s[4][4];
#pragma unroll
        for (int r = 0; r < 4; r++)
#pragma unroll
            for (int c = 0; c < 4; c++) s[r][c] = 0.f;

        for (int d = 0; d < 64; d++) {
            float4 qv = *(float4*)&Qt[d * QT_S + ty * 4];
            float4 kv = *(float4*)&Kt[d * QT_S + tx * 4];
            float qa[4] = {qv.x, qv.y, qv.z, qv.w};
            float ka[4] = {kv.x, kv.y, kv.z, kv.w};
#pragma unroll
            for (int r = 0; r < 4; r++)
#pragma unroll
                for (int c = 0; c < 4; c++)
                    s[r][c] += qa[r] * ka[c];
        }
#pragma unroll
        for (int r = 0; r < 4; r++)
#pragma unroll
            for (int c = 0; c < 4; c++) s[r][c] *= 0.125f;

#pragma unroll
        for (int r = 0; r < 4; r++) {
            float rm = fmaxf(fmaxf(s[r][0], s[r][1]), fmaxf(s[r][2], s[r][3]));
#pragma unroll
            for (int o = 1; o < 16; o <<= 1)
                rm = fmaxf(rm, __shfl_xor_sync(0xffffffffu, rm, o));
            float mnew = fmaxf(m_run[r], rm);
            float corr = __expf(m_run[r] - mnew);
            float rsum = 0.f;
#pragma unroll
            for (int c = 0; c < 4; c++) {
                float p = __expf(s[r][c] - mnew);
                s[r][c] = p; rsum += p;
            }
#pragma unroll
            for (int o = 1; o < 16; o <<= 1)
                rsum += __shfl_xor_sync(0xffffffffu, rsum, o);
            l_run[r] = l_run[r] * corr + rsum;
            m_run[r] = mnew;
#pragma unroll
            for (int d = 0; d < 4; d++) Oacc[r][d] *= corr;
#pragma unroll
            for (int c = 0; c < 4; c++)
                Pt[(tx * 4 + c) * QT_S + ty * 4 + r] = s[r][c];
        }
        __syncthreads();

        for (int j = 0; j < 64; j++) {
            float4 pv = *(float4*)&Pt[j * QT_S + ty * 4];
            float4 vv = *(float4*)&Vs[j * 64 + tx * 4];
            float pa[4] = {pv.x, pv.y, pv.z, pv.w};
            float va[4] = {vv.x, vv.y, vv.z, vv.w};
#pragma unroll
            for (int r = 0; r < 4; r++)
#pragma unroll
                for (int d = 0; d < 4; d++)
                    Oacc[r][d] += pa[r] * va[d];
        }
    }

#pragma unroll
    for (int r = 0; r < 4; r++) {
        float inv = 1.0f / l_run[r];
        int trow = q0 + ty * 4 + r;
        float4 o;
        o.x = Oacc[r][0] * inv;
        o.y = Oacc[r][1] * inv;
        o.z = Oacc[r][2] * inv;
        o.w = Oacc[r][3] * inv;
        *(float4*)(o_out + ((size_t)(b * T_LEN + trow)) * HID + h * 64 + tx * 4) = o;
    }
}

// ============================================================ launch
extern "C" void kernel_launch(void* const* d_in, const int* in_sizes, int n_in,
                              void* d_out, int out_size)
{
    const float* x     = (const float*)d_in[0];
    const float* gamma = (const float*)d_in[1];
    const float* beta  = (const float*)d_in[2];
    const float* w_in  = (const float*)d_in[3];
    const float* w_out = (const float*)d_in[4];
    const float* b_out = (const float*)d_in[5];
    float* out = (float*)d_out;

    void *p_qkvp, *p_o, *p_xh, *p_xl, *p_w1h, *p_w1l, *p_a2h, *p_a2l, *p_w2h, *p_w2l;
    cudaGetSymbolAddress(&p_qkvp, g_qkvp);
    cudaGetSymbolAddress(&p_o, g_o);
    cudaGetSymbolAddress(&p_xh, g_xn_hi);
    cudaGetSymbolAddress(&p_xl, g_xn_lo);
    cudaGetSymbolAddress(&p_w1h, g_w1t_hi);
    cudaGetSymbolAddress(&p_w1l, g_w1t_lo);
    cudaGetSymbolAddress(&p_a2h, g_a2_hi);
    cudaGetSymbolAddress(&p_a2l, g_a2_lo);
    cudaGetSymbolAddress(&p_w2h, g_w2t_hi);
    cudaGetSymbolAddress(&p_w2l, g_w2t_lo);

    float* qkvp = (float*)p_qkvp;
    float* oatt = (float*)p_o;

    cudaFuncSetAttribute(gemm_hmma_kernel,
                         cudaFuncAttributeMaxDynamicSharedMemorySize, GT_SMEM);
    cudaFuncSetAttribute(attn_kernel,
                         cudaFuncAttributeMaxDynamicSharedMemorySize, ATT_SMEM_BYTES);

    // 1. LN + split A1
    ln_kernel<<<M_ROWS, 256>>>(x, gamma, beta,
                               (__nv_bfloat16*)p_xh, (__nv_bfloat16*)p_xl);
    // 2. W1 transpose+split  [1024,7168] -> [7168,1024]
    transpose_split_kernel<<<dim3(QKVP_W / 32, HID / 32), 256>>>(
        w_in, (__nv_bfloat16*)p_w1h, (__nv_bfloat16*)p_w1l, HID, QKVP_W);
    // 3. GEMM1 (HMMA): qkvp = xn @ w_in
    gemm_hmma_kernel<<<dim3(QKVP_W / 128, M_ROWS / 128), 256, GT_SMEM>>>(
        (const __nv_bfloat16*)p_xh, (const __nv_bfloat16*)p_xl,
        (const __nv_bfloat16*)p_w1h, (const __nv_bfloat16*)p_w1l,
        qkvp, nullptr, QKVP_W, HID);
    // 4. rotary
    invf_init_kernel<<<1, 32>>>();
    rotary_kernel<<<32768, 256>>>(qkvp);
    // 5. attention
    attn_kernel<<<dim3(T_LEN / 64, 4 * 16), 256, ATT_SMEM_BYTES>>>(qkvp, oatt);
    // 6. A2 = concat(o, gelu(p)) split
    a2_build_kernel<<<(M_ROWS * 1280) / 256, 256>>>(
        oatt, qkvp, (__nv_bfloat16*)p_a2h, (__nv_bfloat16*)p_a2l);
    // 7. W2 transpose+split  [5120,1024] -> [1024,5120]
    transpose_split_kernel<<<dim3(HID / 32, K2TOT / 32), 256>>>(
        w_out, (__nv_bfloat16*)p_w2h, (__nv_bfloat16*)p_w2l, K2TOT, HID);
    // 8. GEMM2 (HMMA): out = a2 @ w_out + b_out
    gemm_hmma_kernel<<<dim3(HID / 128, M_ROWS / 128), 256, GT_SMEM>>>(
        (const __nv_bfloat16*)p_a2h, (const __nv_bfloat16*)p_a2l,
        (const __nv_bfloat16*)p_w2h, (const __nv_bfloat16*)p_w2l,
        out, b_out, HID, K2TOT);
}

// round 5
// speedup vs baseline: 3.1310x; 1.8760x over previous
#include <cuda_runtime.h>
#include <cuda_bf16.h>
#include <math.h>
#include <cstdint>

// ----------------------------------------------------------------------------
// B=4, T=2048, HIDDEN=1024, HEADS=16, HEAD_DIM=64,  M = B*T = 8192
// GEMM1: [8192,1024]@[1024,7168] -> qkvp    (mma.sync bf16x3, fp32 acc)
// attention: HMMA bf16 flash (this round)
// GEMM2: [8192,5120]@[5120,1024]+bias       (mma.sync bf16x3)
// ----------------------------------------------------------------------------

#define M_ROWS   8192
#define HID      1024
#define QKVP_W   7168
#define T_LEN    2048
#define K2TOT    5120

// ------------------------------- scratch (__device__ globals are allowed)
__device__ __align__(16) float g_qkvp[M_ROWS * QKVP_W];          // 229 MB
__device__ __align__(16) float g_o[M_ROWS * HID];                // 32 MB
__device__ __align__(16) __nv_bfloat16 g_xn_hi[M_ROWS * HID];
__device__ __align__(16) __nv_bfloat16 g_xn_lo[M_ROWS * HID];
__device__ __align__(16) __nv_bfloat16 g_w1t_hi[QKVP_W * HID];   // [N,K]
__device__ __align__(16) __nv_bfloat16 g_w1t_lo[QKVP_W * HID];
__device__ __align__(16) __nv_bfloat16 g_a2_hi[M_ROWS * K2TOT];  // 84 MB
__device__ __align__(16) __nv_bfloat16 g_a2_lo[M_ROWS * K2TOT];
__device__ __align__(16) __nv_bfloat16 g_w2t_hi[HID * K2TOT];    // [N,K]
__device__ __align__(16) __nv_bfloat16 g_w2t_lo[HID * K2TOT];
__device__ __align__(16) __nv_bfloat16 g_qb[M_ROWS * HID];       // [b,h,t,d]
__device__ __align__(16) __nv_bfloat16 g_kb[M_ROWS * HID];
__device__ __align__(16) __nv_bfloat16 g_vb[M_ROWS * HID];
__device__ float g_invf[32];

// ============================================================ PTX helpers
__device__ __forceinline__ uint32_t smem_u32(const void* p) {
    uint32_t a;
    asm("{ .reg .u64 t; cvta.to.shared.u64 t, %1; cvt.u32.u64 %0, t; }"
        : "=r"(a) : "l"(p));
    return a;
}
__device__ __forceinline__ void cp_async16(uint32_t saddr, const void* gaddr) {
    asm volatile("cp.async.cg.shared.global [%0], [%1], 16;"
                 :: "r"(saddr), "l"(gaddr));
}
#define CP_COMMIT() asm volatile("cp.async.commit_group;" ::: "memory")
#define CP_WAIT1()  asm volatile("cp.async.wait_group 1;" ::: "memory")

__device__ __forceinline__ void lds_x4(uint32_t& r0, uint32_t& r1,
                                       uint32_t& r2, uint32_t& r3, uint32_t a) {
    asm volatile("ldmatrix.sync.aligned.m8n8.x4.shared.b16 {%0,%1,%2,%3}, [%4];"
                 : "=r"(r0), "=r"(r1), "=r"(r2), "=r"(r3) : "r"(a));
}
__device__ __forceinline__ void lds_x4t(uint32_t& r0, uint32_t& r1,
                                        uint32_t& r2, uint32_t& r3, uint32_t a) {
    asm volatile("ldmatrix.sync.aligned.m8n8.x4.trans.shared.b16 {%0,%1,%2,%3}, [%4];"
                 : "=r"(r0), "=r"(r1), "=r"(r2), "=r"(r3) : "r"(a));
}
__device__ __forceinline__ void mma_bf16(float* c, const uint32_t* a,
                                         const uint32_t* b) {
    asm volatile(
        "mma.sync.aligned.m16n8k16.row.col.f32.bf16.bf16.f32 "
        "{%0,%1,%2,%3}, {%4,%5,%6,%7}, {%8,%9}, {%0,%1,%2,%3};"
        : "+f"(c[0]), "+f"(c[1]), "+f"(c[2]), "+f"(c[3])
        : "r"(a[0]), "r"(a[1]), "r"(a[2]), "r"(a[3]), "r"(b[0]), "r"(b[1]));
}
__device__ __forceinline__ float ex2(float x) {
    float r; asm("ex2.approx.f32 %0, %1;" : "=f"(r) : "f"(x)); return r;
}
__device__ __forceinline__ uint32_t packbf(float lo, float hi) {
    uint32_t r; asm("cvt.rn.bf16x2.f32 %0, %1, %2;" : "=r"(r) : "f"(hi), "f"(lo));
    return r;
}
// SW128 swizzle for 128B rows: chunk 0..7 of 16B
__device__ __forceinline__ uint32_t sw128(int row, int chunk) {
    return (uint32_t)(row * 128 + ((chunk ^ (row & 7)) * 16));
}

// ============================================================ LayerNorm -> split bf16
__global__ __launch_bounds__(256)
void ln_kernel(const float* __restrict__ x, const float* __restrict__ gamma,
               const float* __restrict__ beta,
               __nv_bfloat16* __restrict__ xh, __nv_bfloat16* __restrict__ xl)
{
    int row = blockIdx.x;
    const float* xr = x + (size_t)row * HID;
    int t = threadIdx.x;
    float v[4];
    float s = 0.f, ss = 0.f;
#pragma unroll
    for (int i = 0; i < 4; i++) {
        v[i] = xr[t + 256 * i];
        s += v[i]; ss += v[i] * v[i];
    }
#pragma unroll
    for (int o = 16; o > 0; o >>= 1) {
        s  += __shfl_xor_sync(0xffffffffu, s, o);
        ss += __shfl_xor_sync(0xffffffffu, ss, o);
    }
    __shared__ float rs[8], rss[8];
    if ((t & 31) == 0) { rs[t >> 5] = s; rss[t >> 5] = ss; }
    __syncthreads();
    float S = 0.f, SS = 0.f;
#pragma unroll
    for (int i = 0; i < 8; i++) { S += rs[i]; SS += rss[i]; }
    float mu  = S * (1.0f / 1024.0f);
    float var = SS * (1.0f / 1024.0f) - mu * mu;
    float inv = rsqrtf(var + 1e-5f);
#pragma unroll
    for (int i = 0; i < 4; i++) {
        int c = t + 256 * i;
        float y = (v[i] - mu) * inv * gamma[c] + beta[c];
        __nv_bfloat16 h = __float2bfloat16(y);
        __nv_bfloat16 l = __float2bfloat16(y - __bfloat162float(h));
        xh[(size_t)row * HID + c] = h;
        xl[(size_t)row * HID + c] = l;
    }
}

// ============================================================ W [K,N] -> [N,K] hi/lo
__global__ __launch_bounds__(256)
void transpose_split_kernel(const float* __restrict__ W,
                            __nv_bfloat16* __restrict__ Th,
                            __nv_bfloat16* __restrict__ Tl, int K, int N)
{
    __shared__ float t[32][33];
    int tx = threadIdx.x & 31, ty = threadIdx.x >> 5;
    int bx = blockIdx.x, by = blockIdx.y;
    int n = bx * 32 + tx;
#pragma unroll
    for (int i = 0; i < 4; i++) {
        int k = by * 32 + ty + i * 8;
        t[ty + i * 8][tx] = W[(size_t)k * N + n];
    }
    __syncthreads();
    int k2 = by * 32 + tx;
#pragma unroll
    for (int i = 0; i < 4; i++) {
        int n2 = bx * 32 + ty + i * 8;
        float v = t[tx][ty + i * 8];
        __nv_bfloat16 h = __float2bfloat16(v);
        __nv_bfloat16 l = __float2bfloat16(v - __bfloat162float(h));
        Th[(size_t)n2 * K + k2] = h;
        Tl[(size_t)n2 * K + k2] = l;
    }
}

// ============================================================ A2 = concat(o, gelu(p)) split
__device__ __forceinline__ float gelu1(float v)
{ return 0.5f * v * (1.0f + erff(v * 0.7071067811865475f)); }

__global__ __launch_bounds__(256)
void a2_build_kernel(const float* __restrict__ o, const float* __restrict__ qkvp,
                     __nv_bfloat16* __restrict__ hi, __nv_bfloat16* __restrict__ lo)
{
    int idx = blockIdx.x * 256 + threadIdx.x;
    int m = idx / 1280, c4 = idx % 1280;
    float4 v;
    if (c4 < 256) {
        v = *(const float4*)(o + (size_t)m * HID + c4 * 4);
    } else {
        v = *(const float4*)(qkvp + (size_t)m * QKVP_W + 2048 + c4 * 4);
        v.x = gelu1(v.x); v.y = gelu1(v.y); v.z = gelu1(v.z); v.w = gelu1(v.w);
    }
    float a[4] = {v.x, v.y, v.z, v.w};
    union { __nv_bfloat16 b[4]; uint2 u; } ph, pl;
#pragma unroll
    for (int i = 0; i < 4; i++) {
        __nv_bfloat16 h = __float2bfloat16(a[i]);
        ph.b[i] = h;
        pl.b[i] = __float2bfloat16(a[i] - __bfloat162float(h));
    }
    *(uint2*)(hi + (size_t)m * K2TOT + c4 * 4) = ph.u;
    *(uint2*)(lo + (size_t)m * K2TOT + c4 * 4) = pl.u;
}

// ============================================================ HMMA GEMM bf16x3
#define STAGE_B  40960
#define OFF_AL   10240
#define OFF_BH   20480
#define OFF_BL   30720
#define GT_SMEM  (3 * STAGE_B)

__global__ __launch_bounds__(256, 1)
void gemm_hmma_kernel(const __nv_bfloat16* __restrict__ Ah,
                      const __nv_bfloat16* __restrict__ Al,
                      const __nv_bfloat16* __restrict__ Bh,
                      const __nv_bfloat16* __restrict__ Bl,
                      float* __restrict__ C, const float* __restrict__ bias,
                      int N, int K)
{
    extern __shared__ __align__(1024) char sm[];
    const uint32_t smb = smem_u32(sm);

    const int tid = threadIdx.x;
    const int lane = tid & 31;
    const int wid = tid >> 5;
    const int wm = wid >> 1;
    const int wn = wid & 1;
    const int m0 = blockIdx.y * 128;
    const int n0 = blockIdx.x * 128;

    const int NK = K >> 5;

    int r0r = tid >> 2, c0 = (tid & 3);
    int r1r = r0r + 64;

    auto load_stage = [&](int kt, int stage) {
        uint32_t sb = smb + stage * STAGE_B;
        int k0 = kt * 32;
        const __nv_bfloat16* pAh0 = Ah + (size_t)(m0 + r0r) * K + k0 + c0 * 8;
        const __nv_bfloat16* pAh1 = Ah + (size_t)(m0 + r1r) * K + k0 + c0 * 8;
        const __nv_bfloat16* pAl0 = Al + (size_t)(m0 + r0r) * K + k0 + c0 * 8;
        const __nv_bfloat16* pAl1 = Al + (size_t)(m0 + r1r) * K + k0 + c0 * 8;
        const __nv_bfloat16* pBh0 = Bh + (size_t)(n0 + r0r) * K + k0 + c0 * 8;
        const __nv_bfloat16* pBh1 = Bh + (size_t)(n0 + r1r) * K + k0 + c0 * 8;
        const __nv_bfloat16* pBl0 = Bl + (size_t)(n0 + r0r) * K + k0 + c0 * 8;
        const __nv_bfloat16* pBl1 = Bl + (size_t)(n0 + r1r) * K + k0 + c0 * 8;
        uint32_t s0 = sb + r0r * 80 + c0 * 16;
        uint32_t s1 = sb + r1r * 80 + c0 * 16;
        cp_async16(s0,           pAh0);  cp_async16(s1,           pAh1);
        cp_async16(s0 + OFF_AL,  pAl0);  cp_async16(s1 + OFF_AL,  pAl1);
        cp_async16(s0 + OFF_BH,  pBh0);  cp_async16(s1 + OFF_BH,  pBh1);
        cp_async16(s0 + OFF_BL,  pBl0);  cp_async16(s1 + OFF_BL,  pBl1);
    };

    float acc[2][8][4];
#pragma unroll
    for (int i = 0; i < 2; i++)
#pragma unroll
        for (int j = 0; j < 8; j++)
#pragma unroll
            for (int k = 0; k < 4; k++) acc[i][j][k] = 0.f;

    load_stage(0, 0); CP_COMMIT();
    load_stage(1, 1); CP_COMMIT();

    const int a_row = (lane & 15);
    const int a_ch  = (lane >> 4);
    const int b_row = ((lane >> 4) << 3) + (lane & 7);
    const int b_ch  = ((lane >> 3) & 1);

    for (int kt = 0; kt < NK; kt++) {
        CP_WAIT1();
        __syncthreads();
        if (kt + 2 < NK) load_stage(kt + 2, (kt + 2) % 3);
        CP_COMMIT();

        uint32_t sb = smb + (kt % 3) * STAGE_B;
#pragma unroll
        for (int s = 0; s < 2; s++) {
            uint32_t ah[2][4], al[2][4];
#pragma unroll
            for (int mi = 0; mi < 2; mi++) {
                uint32_t addr = sb + (wm * 32 + mi * 16 + a_row) * 80
                              + (s * 2 + a_ch) * 16;
                lds_x4(ah[mi][0], ah[mi][1], ah[mi][2], ah[mi][3], addr);
                lds_x4(al[mi][0], al[mi][1], al[mi][2], al[mi][3], addr + OFF_AL);
            }
            uint32_t bh[4][4], bl[4][4];
#pragma unroll
            for (int nt = 0; nt < 4; nt++) {
                uint32_t addr = sb + OFF_BH + (wn * 64 + nt * 16 + b_row) * 80
                              + (s * 2 + b_ch) * 16;
                lds_x4(bh[nt][0], bh[nt][1], bh[nt][2], bh[nt][3], addr);
                lds_x4(bl[nt][0], bl[nt][1], bl[nt][2], bl[nt][3],
                       addr + (OFF_BL - OFF_BH));
            }
#pragma unroll
            for (int mi = 0; mi < 2; mi++)
#pragma unroll
                for (int nt = 0; nt < 4; nt++)
#pragma unroll
                    for (int half = 0; half < 2; half++) {
                        int ni = nt * 2 + half;
                        mma_bf16(acc[mi][ni], ah[mi], &bh[nt][half * 2]);
                        mma_bf16(acc[mi][ni], ah[mi], &bl[nt][half * 2]);
                        mma_bf16(acc[mi][ni], al[mi], &bh[nt][half * 2]);
                    }
        }
    }

#pragma unroll
    for (int mi = 0; mi < 2; mi++) {
        int row = m0 + wm * 32 + mi * 16 + (lane >> 2);
#pragma unroll
        for (int ni = 0; ni < 8; ni++) {
            int col = n0 + wn * 64 + ni * 8 + (lane & 3) * 2;
            float bx = 0.f, by = 0.f;
            if (bias) { bx = bias[col]; by = bias[col + 1]; }
            float2 v0 = { acc[mi][ni][0] + bx, acc[mi][ni][1] + by };
            float2 v1 = { acc[mi][ni][2] + bx, acc[mi][ni][3] + by };
            *(float2*)(C + (size_t)row * N + col) = v0;
            *(float2*)(C + (size_t)(row + 8) * N + col) = v1;
        }
    }
}

// ============================================================ rotary + bf16 pack
__global__ void invf_init_kernel()
{
    int j = threadIdx.x;
    if (j < 32)
        g_invf[j] = (float)exp(-(double)j * (2.302585092994045684 / 8.0));
}

// q/k rotated, v passthrough; all -> bf16 head-major [b,h,t,64]
__global__ __launch_bounds__(256)
void rotpack_kernel(const float* __restrict__ qkvp,
                    __nv_bfloat16* __restrict__ qb,
                    __nv_bfloat16* __restrict__ kb,
                    __nv_bfloat16* __restrict__ vb)
{
    int idx = blockIdx.x * 256 + threadIdx.x;   // ((row*3+tk)*16+h)*32+j
    int j  = idx & 31;
    int t2 = idx >> 5;
    int h  = t2 & 15;
    int t3 = t2 >> 4;
    int tk  = t3 % 3;
    int row = t3 / 3;

    const float* p = qkvp + (size_t)row * QKVP_W + tk * 1024 + h * 64;
    float x1 = p[j], x2 = p[j + 32];
    float o1, o2;
    if (tk < 2) {
        int t = row & 2047;
        float ang = (float)t * g_invf[j];
        float c = cosf(ang), s = sinf(ang);
        o1 = x1 * c - x2 * s;
        o2 = x1 * s + x2 * c;
    } else {
        o1 = x1; o2 = x2;
    }
    __nv_bfloat16* dst = (tk == 0) ? qb : (tk == 1) ? kb : vb;
    int b = row >> 11, t = row & 2047;
    size_t off = ((size_t)(b * 16 + h) * T_LEN + t) * 64;
    dst[off + j]      = __float2bfloat16(o1);
    dst[off + j + 32] = __float2bfloat16(o2);
}

// ============================================================ HMMA flash attention
// CTA: 128 query rows of one (b,h). 8 warps x 16 rows. Key tiles of 64,
// 3-stage cp.async. smem: Q 16KB + 3 x (K 8KB + V 8KB) = 64KB.
#define AT_SMEM 65536
#define AT_SCALE 0.18033688011112042f   /* 0.125 * log2(e) */

__global__ __launch_bounds__(256)
void attn_hmma_kernel(const __nv_bfloat16* __restrict__ qg,
                      const __nv_bfloat16* __restrict__ kg,
                      const __nv_bfloat16* __restrict__ vg,
                      float* __restrict__ o_out)
{
    extern __shared__ __align__(1024) char sm[];
    const uint32_t smb = smem_u32(sm);
    const uint32_t smQ = smb;

    const int tid = threadIdx.x;
    const int lane = tid & 31;
    const int w = tid >> 5;
    const int bh = blockIdx.y;
    const int q0 = blockIdx.x * 128;

    const __nv_bfloat16* qbase = qg + ((size_t)bh * T_LEN + q0) * 64;
    const __nv_bfloat16* kbase = kg + (size_t)bh * T_LEN * 64;
    const __nv_bfloat16* vbase = vg + (size_t)bh * T_LEN * 64;

    // ---- loaders ----
    {   // Q: 128 rows x 128B
        int row = tid >> 1, cb = (tid & 1) * 4;
#pragma unroll
        for (int i = 0; i < 4; i++)
            cp_async16(smQ + sw128(row, cb + i), qbase + row * 64 + (cb + i) * 8);
    }
    auto load_kv = [&](int it, int st) {
        int j0 = it * 64;
        int row = tid >> 2, cb = (tid & 3) * 2;
        uint32_t sb = smb + 16384 + st * 16384;
#pragma unroll
        for (int i = 0; i < 2; i++) {
            cp_async16(sb + sw128(row, cb + i),
                       kbase + (size_t)(j0 + row) * 64 + (cb + i) * 8);
            cp_async16(sb + 8192 + sw128(row, cb + i),
                       vbase + (size_t)(j0 + row) * 64 + (cb + i) * 8);
        }
    };
    load_kv(0, 0); CP_COMMIT();       // G0 = Q + KV0
    load_kv(1, 1); CP_COMMIT();       // G1 = KV1

    CP_WAIT1();                       // G0 done
    __syncthreads();

    // ---- Q fragments (persistent) ----
    uint32_t qf[4][4];
    {
        int a_row = lane & 15, a_ch = lane >> 4;
#pragma unroll
        for (int kk = 0; kk < 4; kk++) {
            uint32_t addr = smQ + sw128(w * 16 + a_row, kk * 2 + a_ch);
            lds_x4(qf[kk][0], qf[kk][1], qf[kk][2], qf[kk][3], addr);
        }
    }

    const int b_row = ((lane >> 4) << 3) + (lane & 7);
    const int b_ch  = (lane >> 3) & 1;

    float acc_o[8][4];
#pragma unroll
    for (int i = 0; i < 8; i++)
#pragma unroll
        for (int j = 0; j < 4; j++) acc_o[i][j] = 0.f;
    float m0 = -1e30f, m1 = -1e30f, l0 = 0.f, l1 = 0.f;

    const int NIT = T_LEN / 64;
    for (int it = 0; it < NIT; it++) {
        if (it) { CP_WAIT1(); __syncthreads(); }
        if (it + 2 < NIT) load_kv(it + 2, (it + 2) % 3);
        CP_COMMIT();

        uint32_t sK = smb + 16384 + (it % 3) * 16384;
        uint32_t sV = sK + 8192;

        // ---- S = Q @ K^T ----
        float s[8][4];
#pragma unroll
        for (int i = 0; i < 8; i++)
#pragma unroll
            for (int j = 0; j < 4; j++) s[i][j] = 0.f;
#pragma unroll
        for (int kk = 0; kk < 4; kk++) {
#pragma unroll
            for (int jt = 0; jt < 4; jt++) {
                uint32_t kf[4];
                lds_x4(kf[0], kf[1], kf[2], kf[3],
                       sK + sw128(jt * 16 + b_row, kk * 2 + b_ch));
                mma_bf16(s[jt * 2],     qf[kk], &kf[0]);
                mma_bf16(s[jt * 2 + 1], qf[kk], &kf[2]);
            }
        }

        // ---- online softmax (exp2 domain, scale folded into FMA) ----
        float mx0 = -1e30f, mx1 = -1e30f;
#pragma unroll
        for (int t = 0; t < 8; t++) {
            mx0 = fmaxf(mx0, fmaxf(s[t][0], s[t][1]));
            mx1 = fmaxf(mx1, fmaxf(s[t][2], s[t][3]));
        }
        mx0 = fmaxf(mx0, __shfl_xor_sync(0xffffffffu, mx0, 1));
        mx0 = fmaxf(mx0, __shfl_xor_sync(0xffffffffu, mx0, 2));
        mx1 = fmaxf(mx1, __shfl_xor_sync(0xffffffffu, mx1, 1));
        mx1 = fmaxf(mx1, __shfl_xor_sync(0xffffffffu, mx1, 2));
        float mn0 = fmaxf(m0, mx0), mn1 = fmaxf(m1, mx1);
        float c0 = ex2((m0 - mn0) * AT_SCALE);
        float c1 = ex2((m1 - mn1) * AT_SCALE);
        float a0 = mn0 * AT_SCALE, a1 = mn1 * AT_SCALE;

        float rs0 = 0.f, rs1 = 0.f;
        uint32_t pf[4][4];
#pragma unroll
        for (int t = 0; t < 8; t++) {
            float p0 = ex2(fmaf(s[t][0], AT_SCALE, -a0));
            float p1 = ex2(fmaf(s[t][1], AT_SCALE, -a0));
            float p2 = ex2(fmaf(s[t][2], AT_SCALE, -a1));
            float p3 = ex2(fmaf(s[t][3], AT_SCALE, -a1));
            rs0 += p0 + p1; rs1 += p2 + p3;
            pf[t >> 1][(t & 1) * 2]     = packbf(p0, p1);
            pf[t >> 1][(t & 1) * 2 + 1] = packbf(p2, p3);
        }
        rs0 += __shfl_xor_sync(0xffffffffu, rs0, 1);
        rs0 += __shfl_xor_sync(0xffffffffu, rs0, 2);
        rs1 += __shfl_xor_sync(0xffffffffu, rs1, 1);
        rs1 += __shfl_xor_sync(0xffffffffu, rs1, 2);
        l0 = l0 * c0 + rs0;
        l1 = l1 * c1 + rs1;
        m0 = mn0; m1 = mn1;
#pragma unroll
        for (int dt = 0; dt < 8; dt++) {
            acc_o[dt][0] *= c0; acc_o[dt][1] *= c0;
            acc_o[dt][2] *= c1; acc_o[dt][3] *= c1;
        }

        // ---- O += P @ V ----
#pragma unroll
        for (int kk = 0; kk < 4; kk++) {
#pragma unroll
            for (int dc = 0; dc < 4; dc++) {
                uint32_t vf[4];
                lds_x4t(vf[0], vf[1], vf[2], vf[3],
                        sV + sw128(kk * 16 + (lane & 15), dc * 2 + (lane >> 4)));
                mma_bf16(acc_o[dc * 2],     pf[kk], &vf[0]);
                mma_bf16(acc_o[dc * 2 + 1], pf[kk], &vf[2]);
            }
        }
    }

    // ---- epilogue ----
    float i0 = 1.0f / l0, i1 = 1.0f / l1;
    int b = bh >> 4, h = bh & 15;
    int r0g = q0 + w * 16 + (lane >> 2);
    float* op = o_out + ((size_t)b * T_LEN + r0g) * HID + h * 64 + (lane & 3) * 2;
#pragma unroll
    for (int dt = 0; dt < 8; dt++) {
        float2 v0 = { acc_o[dt][0] * i0, acc_o[dt][1] * i0 };
        float2 v1 = { acc_o[dt][2] * i1, acc_o[dt][3] * i1 };
        *(float2*)(op + dt * 8) = v0;
        *(float2*)(op + 8 * HID + dt * 8) = v1;
    }
}

// ============================================================ launch
extern "C" void kernel_launch(void* const* d_in, const int* in_sizes, int n_in,
                              void* d_out, int out_size)
{
    const float* x     = (const float*)d_in[0];
    const float* gamma = (const float*)d_in[1];
    const float* beta  = (const float*)d_in[2];
    const float* w_in  = (const float*)d_in[3];
    const float* w_out = (const float*)d_in[4];
    const float* b_out = (const float*)d_in[5];
    float* out = (float*)d_out;

    void *p_qkvp, *p_o, *p_xh, *p_xl, *p_w1h, *p_w1l, *p_a2h, *p_a2l, *p_w2h, *p_w2l;
    void *p_qb, *p_kb, *p_vb;
    cudaGetSymbolAddress(&p_qkvp, g_qkvp);
    cudaGetSymbolAddress(&p_o, g_o);
    cudaGetSymbolAddress(&p_xh, g_xn_hi);
    cudaGetSymbolAddress(&p_xl, g_xn_lo);
    cudaGetSymbolAddress(&p_w1h, g_w1t_hi);
    cudaGetSymbolAddress(&p_w1l, g_w1t_lo);
    cudaGetSymbolAddress(&p_a2h, g_a2_hi);
    cudaGetSymbolAddress(&p_a2l, g_a2_lo);
    cudaGetSymbolAddress(&p_w2h, g_w2t_hi);
    cudaGetSymbolAddress(&p_w2l, g_w2t_lo);
    cudaGetSymbolAddress(&p_qb, g_qb);
    cudaGetSymbolAddress(&p_kb, g_kb);
    cudaGetSymbolAddress(&p_vb, g_vb);

    float* qkvp = (float*)p_qkvp;
    float* oatt = (float*)p_o;

    cudaFuncSetAttribute(gemm_hmma_kernel,
                         cudaFuncAttributeMaxDynamicSharedMemorySize, GT_SMEM);
    cudaFuncSetAttribute(attn_hmma_kernel,
                         cudaFuncAttributeMaxDynamicSharedMemorySize, AT_SMEM);

    // 1. LN + split A1
    ln_kernel<<<M_ROWS, 256>>>(x, gamma, beta,
                               (__nv_bfloat16*)p_xh, (__nv_bfloat16*)p_xl);
    // 2. W1 transpose+split
    transpose_split_kernel<<<dim3(QKVP_W / 32, HID / 32), 256>>>(
        w_in, (__nv_bfloat16*)p_w1h, (__nv_bfloat16*)p_w1l, HID, QKVP_W);
    // 3. GEMM1 (HMMA)
    gemm_hmma_kernel<<<dim3(QKVP_W / 128, M_ROWS / 128), 256, GT_SMEM>>>(
        (const __nv_bfloat16*)p_xh, (const __nv_bfloat16*)p_xl,
        (const __nv_bfloat16*)p_w1h, (const __nv_bfloat16*)p_w1l,
        qkvp, nullptr, QKVP_W, HID);
    // 4. rotary + bf16 pack (q,k rotated; v passthrough)
    invf_init_kernel<<<1, 32>>>();
    rotpack_kernel<<<(M_ROWS * 3 * 16 * 32) / 256, 256>>>(
        qkvp, (__nv_bfloat16*)p_qb, (__nv_bfloat16*)p_kb, (__nv_bfloat16*)p_vb);
    // 5. attention (HMMA flash)
    attn_hmma_kernel<<<dim3(T_LEN / 128, 4 * 16), 256, AT_SMEM>>>(
        (const __nv_bfloat16*)p_qb, (const __nv_bfloat16*)p_kb,
        (const __nv_bfloat16*)p_vb, oatt);
    // 6. A2 = concat(o, gelu(p)) split
    a2_build_kernel<<<(M_ROWS * 1280) / 256, 256>>>(
        oatt, qkvp, (__nv_bfloat16*)p_a2h, (__nv_bfloat16*)p_a2l);
    // 7. W2 transpose+split
    transpose_split_kernel<<<dim3(HID / 32, K2TOT / 32), 256>>>(
        w_out, (__nv_bfloat16*)p_w2h, (__nv_bfloat16*)p_w2l, K2TOT, HID);
    // 8. GEMM2 (HMMA)
    gemm_hmma_kernel<<<dim3(HID / 128, M_ROWS / 128), 256, GT_SMEM>>>(
        (const __nv_bfloat16*)p_a2h, (const __nv_bfloat16*)p_a2l,
        (const __nv_bfloat16*)p_w2h, (const __nv_bfloat16*)p_w2l,
        out, b_out, HID, K2TOT);
}